// round 13
// baseline (speedup 1.0000x reference)
#include <cuda_runtime.h>
#include <cuda_fp16.h>
#include <cstdint>

#define H    448
#define HH   (448*448)
#define CIN  64
#define COUT 64
#define NB   32
#define BS   14
#define NTHR 512

// combined halo: 16 rows x 32 cols, 144B pixel stride
#define HROWS 16
#define HCOLS 32

// ---- dynamic smem layout (bytes) ----
#define OFF_HALO  0                  // 512 pos x 144B = 73728
#define OFF_WTAB  73728              // 73728B W table (staged after raw dead)
#define OFF_RAWA  73728              // 16 cin x 16 rows x 40 f32 = 40960
#define OFF_RAWB  114688             // 40960
#define OFF_BIAS  155648             // 64 f32
#define SMEM_TOTAL 155904
// epilogue aliases [0, 118272) = 448 px x 66 f32 (halo/W dead by then)

#define RAWP  640                    // floats per cin plane (16*40)

__device__ unsigned char g_active[4 * NB * NB];
// W table, ldmatrix-native: offset(tap,nt,ks,half,row) = (((tap*8+nt)*4+ks)*2+half)*128 + row*16
__device__ __align__(16) unsigned char g_wtab[9 * 8 * 4 * 2 * 128];

// ---------------- helpers ----------------
__device__ __forceinline__ uint32_t smem_u32(const void* p) {
    uint32_t a;
    asm("{ .reg .u64 t; cvta.to.shared.u64 t, %1; cvt.u32.u64 %0, t; }" : "=r"(a) : "l"(p));
    return a;
}
__device__ __forceinline__ void ldsm_x4(uint32_t* r, uint32_t addr) {
    asm volatile("ldmatrix.sync.aligned.m8n8.x4.shared.b16 {%0,%1,%2,%3}, [%4];"
        : "=r"(r[0]), "=r"(r[1]), "=r"(r[2]), "=r"(r[3]) : "r"(addr));
}
__device__ __forceinline__ void mma16816(float* d, const uint32_t* a, uint32_t b0, uint32_t b1) {
    asm volatile("mma.sync.aligned.m16n8k16.row.col.f32.f16.f16.f32 "
        "{%0,%1,%2,%3}, {%4,%5,%6,%7}, {%8,%9}, {%0,%1,%2,%3};"
        : "+f"(d[0]), "+f"(d[1]), "+f"(d[2]), "+f"(d[3])
        : "r"(a[0]), "r"(a[1]), "r"(a[2]), "r"(a[3]), "r"(b0), "r"(b1));
}
__device__ __forceinline__ uint32_t pack2(__half a, __half b) {
    return ((uint32_t)__half_as_ushort(b) << 16) | __half_as_ushort(a);
}
__device__ __forceinline__ void cp_async16(uint32_t dst, const void* src, bool pred) {
    asm volatile("cp.async.cg.shared.global [%0], [%1], 16, %2;"
        :: "r"(dst), "l"(src), "r"(pred ? 16u : 0u) : "memory");
}

// ---------------- Kernel 0: combined prep (W table + block activity) ----------------
__global__ void sbnet_prep_kernel(const float* __restrict__ w,
                                  const float* __restrict__ mask, int n_total) {
    if (blockIdx.x < 18) {
        int i = blockIdx.x * 256 + threadIdx.x;      // 0..4607 16B rows
        int tap = i / 512;
        int r   = i & 511;
        int nt = r >> 6, ks = (r >> 4) & 3, half = (r >> 3) & 1, row = r & 7;
        int co = nt * 8 + row;
        int k0 = ks * 16 + half * 8;
        const float* wc = w + ((size_t)co * CIN + k0) * 9 + tap;
        uint32_t u[4];
        #pragma unroll
        for (int c = 0; c < 4; ++c)
            u[c] = pack2(__float2half(wc[(size_t)(2 * c) * 9]),
                         __float2half(wc[(size_t)(2 * c + 1) * 9]));
        *(uint4*)(g_wtab + (size_t)i * 16) = make_uint4(u[0], u[1], u[2], u[3]);
        return;
    }
    int idx = (blockIdx.x - 18) * 256 + threadIdx.x;
    if (idx >= n_total) return;
    int bx = idx % NB;
    int by = (idx / NB) % NB;
    int n  = idx / (NB * NB);
    int r0 = by * BS - 1, c0 = bx * BS - 1;
    float m = -1e30f;
    for (int r = 0; r < 16; ++r) {
        int rr = r0 + r;
        if (rr < 0 || rr >= H) continue;
        const float* mrow = mask + ((long)n * H + rr) * H;
        int clo = (c0 < 0) ? 1 : 0;
        int chi = (c0 + 16 > H) ? 15 : 16;
        for (int c = clo; c < chi; ++c) m = fmaxf(m, mrow[c0 + c]);
    }
    g_active[idx] = (m > 0.5f) ? 1 : 0;
}

// ---------------- Kernel 1: fused HMMA conv, 2 blocks per CTA ----------------
__global__ void __launch_bounds__(NTHR, 1)
sbnet_mma_kernel(const float* __restrict__ x, const float* __restrict__ bias,
                 float* __restrict__ out) {
    extern __shared__ char smem[];
    const int tid  = threadIdx.x;
    const int wid  = tid >> 5;
    const int lane = tid & 31;
    const int px = blockIdx.x & 15;      // block pair index along x
    const int by = blockIdx.x >> 4;
    const int n  = blockIdx.y;

    const int act0 = g_active[n * NB * NB + by * NB + px * 2];
    const int act1 = g_active[n * NB * NB + by * NB + px * 2 + 1];

    const int ly0 = lane / BS;
    const int lx0 = lane - ly0 * BS;
    const int hwid = wid >> 3;           // which half this warp stores (epilogue)
    const int cwid = wid & 7;

    if (!(act0 | act1)) {
        // zero both 64 x 14 x 14 blocks
        #pragma unroll 1
        for (int cog = 0; cog < 8; ++cog) {
            int co = cwid + cog * 8;
            float* op = out + ((size_t)(n * COUT + co)) * HH + (size_t)(by * BS) * H
                            + (px * 2 + hwid) * BS;
            int yy = ly0, xq = lx0;
            #pragma unroll
            for (int rnd = 0; rnd < 7; ++rnd) {
                if (rnd * 32 + lane < BS * BS)
                    op[(size_t)yy * H + xq] = 0.0f;
                yy += 2; xq += 4;
                if (xq >= BS) { xq -= BS; ++yy; }
            }
        }
        return;
    }

    const uint32_t smem_base = smem_u32(smem);
    float* s_bias = (float*)(smem + OFF_BIAS);
    if (tid < COUT) s_bias[tid] = bias[tid];

    const int r0 = by * BS - 1;
    const int c0 = px * 2 * BS - 1;          // leftmost halo col (global)
    const int cb0 = (c0 < 0) ? 0 : (c0 & ~3);
    const int coff = c0 - cb0;               // raw col = coff + xx
    const uint32_t halo = smem_base + OFF_HALO;

    auto issue_load = [&](int chunk, uint32_t rb) {
        const float* xb = x + ((size_t)(n * CIN + chunk * 16)) * HH;
        #pragma unroll
        for (int it = 0; it < 5; ++it) {
            int i = it * NTHR + tid;         // 0..2559
            int j = i % 10;
            int rest = i / 10;
            int y  = rest & 15;
            int ci = rest >> 4;
            int rr = r0 + y;
            int s  = cb0 + j * 4;
            bool inb = (rr >= 0 && rr < H && s < H);
            const float* src = xb + (size_t)ci * HH + (inb ? (size_t)rr * H + s : 0);
            cp_async16(rb + (uint32_t)(ci * RAWP + y * 40 + j * 4) * 4, src, inb);
        }
        asm volatile("cp.async.commit_group;" ::: "memory");
    };

    auto convert = [&](int chunk, const float* raw) {
        int pos = tid;                       // exactly 512 positions
        int y  = pos >> 5;
        int xx = pos & 31;
        int cc = c0 + xx;
        bool ok = (cc >= 0 && cc < H);
        int idx = ok ? (y * 40 + coff + xx) : 0;
        uint32_t hu[8];
        #pragma unroll
        for (int k = 0; k < 8; ++k) {
            float v0 = raw[(2 * k) * RAWP + idx];
            float v1 = raw[(2 * k + 1) * RAWP + idx];
            if (!ok) { v0 = 0.0f; v1 = 0.0f; }
            hu[k] = pack2(__float2half(v0), __float2half(v1));
        }
        char* dst = smem + OFF_HALO + pos * 144 + chunk * 32;
        *(uint4*)dst        = make_uint4(hu[0], hu[1], hu[2], hu[3]);
        *(uint4*)(dst + 16) = make_uint4(hu[4], hu[5], hu[6], hu[7]);
    };

    const float* rawA = (const float*)(smem + OFF_RAWA);
    const float* rawB = (const float*)(smem + OFF_RAWB);
    const uint32_t rbA = smem_base + OFF_RAWA;
    const uint32_t rbB = smem_base + OFF_RAWB;

    issue_load(0, rbA);
    issue_load(1, rbB);
    asm volatile("cp.async.wait_group 1;" ::: "memory");
    __syncthreads();
    convert(0, rawA);
    __syncthreads();
    issue_load(2, rbA);
    asm volatile("cp.async.wait_group 1;" ::: "memory");
    __syncthreads();
    convert(1, rawB);
    __syncthreads();
    issue_load(3, rbB);
    asm volatile("cp.async.wait_group 1;" ::: "memory");
    __syncthreads();
    convert(2, rawA);
    asm volatile("cp.async.wait_group 0;" ::: "memory");
    __syncthreads();
    convert(3, rawB);
    __syncthreads();               // raw dead -> stage W into its region

    // ---- stage W table (73728B, 4608 x 16B) ----
    {
        const uint4* wsrc = (const uint4*)g_wtab;
        uint32_t wdst = smem_base + OFF_WTAB;
        #pragma unroll
        for (int it = 0; it < 9; ++it) {
            int i = it * NTHR + tid;
            cp_async16(wdst + (uint32_t)i * 16, wsrc + i, true);
        }
        asm volatile("cp.async.commit_group;" ::: "memory");
        asm volatile("cp.async.wait_group 0;" ::: "memory");
        __syncthreads();
    }

    // ---- tile assignment: 28 tiles over 16 warps -> 12 warps x2 + 4 warps x1 ----
    const int t0  = (wid < 12) ? wid * 2 : 24 + (wid - 12);
    const bool two = (wid < 12);
    const int th  = (t0 >= 14);          // half of this warp's tiles (no straddle)
    const int yb  = t0 - th * 14;
    const int colbase = th * 14;

    const int cA = lane & 15;
    const uint32_t kbase = (uint32_t)(lane >> 4) * 16;
    const uint32_t wlane = smem_base + OFF_WTAB +
        (uint32_t)(lane >> 4) * 1024 + (uint32_t)((lane >> 3) & 1) * 128 +
        (uint32_t)(lane & 7) * 16;

    float acc[2][8][4];
    #pragma unroll
    for (int mt = 0; mt < 2; ++mt)
        #pragma unroll
        for (int nt = 0; nt < 8; ++nt)
            #pragma unroll
            for (int q = 0; q < 4; ++q) acc[mt][nt][q] = 0.0f;

    #pragma unroll 1
    for (int tap = 0; tap < 9; ++tap) {
        const int dy = tap / 3, dx = tap - dy * 3;
        const uint32_t a0 = halo + (uint32_t)((yb + dy) * HCOLS + colbase + cA + dx) * 144 + kbase;
        const uint32_t a1 = a0 + HCOLS * 144;
        const uint32_t wt = wlane + (uint32_t)tap * 8192;

        #pragma unroll
        for (int ks = 0; ks < 4; ++ks) {
            uint32_t ah[2][4];
            uint32_t bb[4][4];
            ldsm_x4(ah[0], a0 + ks * 32);
            if (two) ldsm_x4(ah[1], a1 + ks * 32);
            #pragma unroll
            for (int np = 0; np < 4; ++np)
                ldsm_x4(bb[np], wt + (uint32_t)np * 2048 + (uint32_t)ks * 256);
            #pragma unroll
            for (int nt = 0; nt < 8; ++nt)
                mma16816(acc[0][nt], ah[0], bb[nt >> 1][(nt & 1) * 2], bb[nt >> 1][(nt & 1) * 2 + 1]);
            if (two) {
                #pragma unroll
                for (int nt = 0; nt < 8; ++nt)
                    mma16816(acc[1][nt], ah[1], bb[nt >> 1][(nt & 1) * 2], bb[nt >> 1][(nt & 1) * 2 + 1]);
            }
        }
    }

    // ---- epilogue: accums -> smem transpose -> coalesced gmem ----
    __syncthreads();               // halo/W dead -> epi aliasing safe
    float* epi = (float*)smem;     // [448][66]
    {
        const int g  = lane >> 2;
        const int tg = lane & 3;
        #pragma unroll
        for (int mt = 0; mt < 2; ++mt) {
            if (mt == 0 || two) {
                int tile = t0 + mt;
                #pragma unroll
                for (int nt = 0; nt < 8; ++nt) {
                    int p  = tile * 16 + g;
                    int co = nt * 8 + 2 * tg;
                    *(float2*)&epi[p * 66 + co]       = make_float2(acc[mt][nt][0], acc[mt][nt][1]);
                    *(float2*)&epi[(p + 8) * 66 + co] = make_float2(acc[mt][nt][2], acc[mt][nt][3]);
                }
            }
        }
    }
    __syncthreads();

    const int hact = hwid ? act1 : act0;
    #pragma unroll 1
    for (int cog = 0; cog < 8; ++cog) {
        int co = cwid + cog * 8;
        float bv = s_bias[co];
        float* op = out + ((size_t)(n * COUT + co)) * HH + (size_t)(by * BS) * H
                        + (px * 2 + hwid) * BS;
        int yy = ly0, xq = lx0;
        #pragma unroll
        for (int rnd = 0; rnd < 7; ++rnd) {
            if (rnd * 32 + lane < BS * BS) {
                float val = hact ? (epi[((hwid * 14 + yy) * 16 + xq) * 66 + co] + bv) : 0.0f;
                op[(size_t)yy * H + xq] = val;
            }
            yy += 2; xq += 4;
            if (xq >= BS) { xq -= BS; ++yy; }
        }
    }
}

extern "C" void kernel_launch(void* const* d_in, const int* in_sizes, int n_in,
                              void* d_out, int out_size) {
    const float* x    = (const float*)d_in[0];
    const float* mask = (const float*)d_in[1];
    const float* w    = (const float*)d_in[2];
    const float* bias = (const float*)d_in[3];
    float* out = (float*)d_out;

    int N = in_sizes[0] / (CIN * H * H);   // 4
    int nblk = N * NB * NB;

    cudaFuncSetAttribute(sbnet_mma_kernel,
                         cudaFuncAttributeMaxDynamicSharedMemorySize, SMEM_TOTAL);

    sbnet_prep_kernel<<<18 + (nblk + 255) / 256, 256>>>(w, mask, nblk);
    sbnet_mma_kernel<<<dim3(NB * NB / 2, (unsigned)N), NTHR, SMEM_TOTAL>>>(x, bias, out);
}

// round 14
// speedup vs baseline: 1.1615x; 1.1615x over previous
#include <cuda_runtime.h>
#include <cuda_fp16.h>
#include <cstdint>

#define H    448
#define HH   (448*448)
#define CIN  64
#define COUT 64
#define NB   32
#define BS   14
#define HALW 18
#define HALR 16
#define NPOS (HALR*HALW)             // 288
#define NTHR 256

// ---- dynamic smem layout (bytes) ----
#define OFF_HALO  0                  // 288 pos x 144B
#define OFF_WTAB  41472              // 73728B W table (ldsm layout)
#define OFF_RAWA  41472              // aliases WTAB[0,24576) during halo build
#define OFF_RAWB  66048              // aliases WTAB[24576,49152)
#define OFF_BIAS  115200             // 64 f32
#define SMEM_TOTAL 115456
// epilogue aliases [0, 59136) = 224 x 66 f32

#define RAWP  384                    // floats per cin plane (16*24)
#define WPART1 24576                 // W bytes stageable after convert(2)

__device__ unsigned char g_active[4 * NB * NB];
// W table, ldmatrix-native: offset(tap,nt,ks,half,row)= (((tap*8+nt)*4+ks)*2+half)*128 + row*16
__device__ __align__(16) unsigned char g_wtab[9 * 8 * 4 * 2 * 128];

// balanced tile tables (nibble per wid)
#define STARTS_A 0xCBA86420u
#define COUNTS_A 0x21122222u
#define STARTS_B 0xCA876420u
#define COUNTS_B 0x22211222u

// ---------------- helpers ----------------
__device__ __forceinline__ uint32_t smem_u32(const void* p) {
    uint32_t a;
    asm("{ .reg .u64 t; cvta.to.shared.u64 t, %1; cvt.u32.u64 %0, t; }" : "=r"(a) : "l"(p));
    return a;
}
__device__ __forceinline__ void ldsm_x4(uint32_t* r, uint32_t addr) {
    asm volatile("ldmatrix.sync.aligned.m8n8.x4.shared.b16 {%0,%1,%2,%3}, [%4];"
        : "=r"(r[0]), "=r"(r[1]), "=r"(r[2]), "=r"(r[3]) : "r"(addr));
}
__device__ __forceinline__ void mma16816(float* d, const uint32_t* a, uint32_t b0, uint32_t b1) {
    asm volatile("mma.sync.aligned.m16n8k16.row.col.f32.f16.f16.f32 "
        "{%0,%1,%2,%3}, {%4,%5,%6,%7}, {%8,%9}, {%0,%1,%2,%3};"
        : "+f"(d[0]), "+f"(d[1]), "+f"(d[2]), "+f"(d[3])
        : "r"(a[0]), "r"(a[1]), "r"(a[2]), "r"(a[3]), "r"(b0), "r"(b1));
}
__device__ __forceinline__ uint32_t pack2(__half a, __half b) {
    return ((uint32_t)__half_as_ushort(b) << 16) | __half_as_ushort(a);
}
__device__ __forceinline__ void cp_async16(uint32_t dst, const void* src, bool pred) {
    asm volatile("cp.async.cg.shared.global [%0], [%1], 16, %2;"
        :: "r"(dst), "l"(src), "r"(pred ? 16u : 0u) : "memory");
}

// ---------------- Kernel 0: combined prep (W table + block activity) ----------------
__global__ void sbnet_prep_kernel(const float* __restrict__ w,
                                  const float* __restrict__ mask, int n_total) {
    if (blockIdx.x < 18) {
        int i = blockIdx.x * 256 + threadIdx.x;
        int tap = i / 512;
        int r   = i & 511;
        int nt = r >> 6, ks = (r >> 4) & 3, half = (r >> 3) & 1, row = r & 7;
        int co = nt * 8 + row;
        int k0 = ks * 16 + half * 8;
        const float* wc = w + ((size_t)co * CIN + k0) * 9 + tap;
        uint32_t u[4];
        #pragma unroll
        for (int c = 0; c < 4; ++c)
            u[c] = pack2(__float2half(wc[(size_t)(2 * c) * 9]),
                         __float2half(wc[(size_t)(2 * c + 1) * 9]));
        *(uint4*)(g_wtab + (size_t)i * 16) = make_uint4(u[0], u[1], u[2], u[3]);
        return;
    }
    int idx = (blockIdx.x - 18) * 256 + threadIdx.x;
    if (idx >= n_total) return;
    int bx = idx % NB;
    int by = (idx / NB) % NB;
    int n  = idx / (NB * NB);
    int r0 = by * BS - 1, c0 = bx * BS - 1;
    float m = -1e30f;
    for (int r = 0; r < 16; ++r) {
        int rr = r0 + r;
        if (rr < 0 || rr >= H) continue;
        const float* mrow = mask + ((long)n * H + rr) * H;
        int clo = (c0 < 0) ? 1 : 0;
        int chi = (c0 + 16 > H) ? 15 : 16;
        for (int c = clo; c < chi; ++c) m = fmaxf(m, mrow[c0 + c]);
    }
    g_active[idx] = (m > 0.5f) ? 1 : 0;
}

// ---------------- Kernel 1: fused HMMA block conv ----------------
__global__ void __launch_bounds__(NTHR, 2)
sbnet_mma_kernel(const float* __restrict__ x, const float* __restrict__ bias,
                 float* __restrict__ out) {
    extern __shared__ char smem[];
    const int tid  = threadIdx.x;
    const int wid  = tid >> 5;
    const int lane = tid & 31;
    const int bx = blockIdx.x % NB;
    const int by = blockIdx.x / NB;
    const int n  = blockIdx.y;

    const int ly0 = lane / BS;
    const int lx0 = lane - ly0 * BS;

    if (!g_active[n * NB * NB + blockIdx.x]) {
        #pragma unroll 1
        for (int cog = 0; cog < 8; ++cog) {
            int co = wid + cog * 8;
            float* op = out + ((size_t)(n * COUT + co)) * HH + (size_t)(by * BS) * H + bx * BS;
            int yy = ly0, xq = lx0;
            #pragma unroll
            for (int rnd = 0; rnd < 7; ++rnd) {
                if (rnd * 32 + lane < BS * BS)
                    op[(size_t)yy * H + xq] = 0.0f;
                yy += 2; xq += 4;
                if (xq >= BS) { xq -= BS; ++yy; }
            }
        }
        return;
    }

    const uint32_t smem_base = smem_u32(smem);
    float* s_bias = (float*)(smem + OFF_BIAS);
    if (tid < COUT) s_bias[tid] = bias[tid];

    const int r0 = by * BS - 1, c0 = bx * BS - 1;
    const int cb0 = (c0 < 0) ? 0 : (c0 & ~3);
    const int coff = c0 - cb0;
    const uint32_t halo = smem_base + OFF_HALO;

    auto issue_load = [&](int chunk, uint32_t rb) {
        const float* xb = x + ((size_t)(n * CIN + chunk * 16)) * HH;
        #pragma unroll
        for (int it = 0; it < 6; ++it) {
            int i = it * 256 + tid;
            int j = i % 6;
            int rest = i / 6;
            int y  = rest & 15;
            int ci = rest >> 4;
            int rr = r0 + y;
            int s  = cb0 + j * 4;
            bool inb = (rr >= 0 && rr < H && s < H);
            const float* src = xb + (size_t)ci * HH + (inb ? (size_t)rr * H + s : 0);
            cp_async16(rb + (uint32_t)(ci * RAWP + y * 24 + j * 4) * 4, src, inb);
        }
        asm volatile("cp.async.commit_group;" ::: "memory");
    };

    auto convert = [&](int chunk, const float* raw) {
        #pragma unroll 1
        for (int pos = tid; pos < NPOS; pos += NTHR) {
            int y  = pos / HALW;
            int xx = pos - y * HALW;
            int cc = c0 + xx;
            bool ok = (cc >= 0 && cc < H);
            int idx = ok ? (y * 24 + coff + xx) : 0;
            uint32_t hu[8];
            #pragma unroll
            for (int k = 0; k < 8; ++k) {
                float v0 = raw[(2 * k) * RAWP + idx];
                float v1 = raw[(2 * k + 1) * RAWP + idx];
                if (!ok) { v0 = 0.0f; v1 = 0.0f; }
                hu[k] = pack2(__float2half(v0), __float2half(v1));
            }
            char* dst = smem + OFF_HALO + pos * 144 + chunk * 32;
            *(uint4*)dst        = make_uint4(hu[0], hu[1], hu[2], hu[3]);
            *(uint4*)(dst + 16) = make_uint4(hu[4], hu[5], hu[6], hu[7]);
        }
    };

    const float* rawA = (const float*)(smem + OFF_RAWA);
    const float* rawB = (const float*)(smem + OFF_RAWB);
    const uint32_t rbA = smem_base + OFF_RAWA;
    const uint32_t rbB = smem_base + OFF_RAWB;
    const uint4* wsrc = (const uint4*)g_wtab;
    const uint32_t wdst = smem_base + OFF_WTAB;

    issue_load(0, rbA);
    issue_load(1, rbB);
    asm volatile("cp.async.wait_group 1;" ::: "memory");
    __syncthreads();
    convert(0, rawA);
    __syncthreads();
    issue_load(2, rbA);
    asm volatile("cp.async.wait_group 1;" ::: "memory");
    __syncthreads();
    convert(1, rawB);
    __syncthreads();
    issue_load(3, rbB);
    asm volatile("cp.async.wait_group 1;" ::: "memory");
    __syncthreads();
    convert(2, rawA);                 // rawA now dead
    __syncthreads();                  // all reads of rawA done
    // ---- stage W part 1 (24576B into dead rawA region), overlaps chunk-3 wait ----
    {
        #pragma unroll
        for (int it = 0; it < 6; ++it) {
            int i = it * 256 + tid;   // 0..1535 16B rows
            cp_async16(wdst + (uint32_t)i * 16, wsrc + i, true);
        }
        asm volatile("cp.async.commit_group;" ::: "memory");
    }
    asm volatile("cp.async.wait_group 1;" ::: "memory");   // chunk 3 done (W1 may pend)
    __syncthreads();
    convert(3, rawB);                 // rawB now dead
    __syncthreads();
    // ---- stage W part 2 (49152B) ----
    {
        #pragma unroll
        for (int it = 0; it < 12; ++it) {
            int i = 1536 + it * 256 + tid;   // rows 1536..4607
            cp_async16(wdst + (uint32_t)i * 16, wsrc + i, true);
        }
        asm volatile("cp.async.commit_group;" ::: "memory");
        asm volatile("cp.async.wait_group 0;" ::: "memory");
        __syncthreads();
    }

    // ---- balanced tile assignment ----
    const int parity = (blockIdx.x + blockIdx.y) & 1;
    const uint32_t starts = parity ? STARTS_B : STARTS_A;
    const uint32_t counts = parity ? COUNTS_B : COUNTS_A;
    const int t0  = (starts >> (4 * wid)) & 15;
    const bool two = (((counts >> (4 * wid)) & 15) == 2);

    const int cA = lane & 15;
    const uint32_t kbase = (uint32_t)(lane >> 4) * 16;
    const uint32_t wlane = smem_base + OFF_WTAB +
        (uint32_t)(lane >> 4) * 1024 + (uint32_t)((lane >> 3) & 1) * 128 +
        (uint32_t)(lane & 7) * 16;

    float acc[2][8][4];
    #pragma unroll
    for (int mt = 0; mt < 2; ++mt)
        #pragma unroll
        for (int nt = 0; nt < 8; ++nt)
            #pragma unroll
            for (int q = 0; q < 4; ++q) acc[mt][nt][q] = 0.0f;

    // dy loop (unroll 1) x dx fully unrolled: 3-tap scheduling window
    #pragma unroll 1
    for (int dy = 0; dy < 3; ++dy) {
        const uint32_t abase = halo + (uint32_t)((t0 + dy) * HALW + cA) * 144 + kbase;
        const uint32_t wbase = wlane + (uint32_t)(dy * 3) * 8192;
        #pragma unroll
        for (int dx = 0; dx < 3; ++dx) {
            const uint32_t a0 = abase + (uint32_t)dx * 144;
            const uint32_t a1 = a0 + HALW * 144;
            const uint32_t wt = wbase + (uint32_t)dx * 8192;
            #pragma unroll
            for (int ks = 0; ks < 4; ++ks) {
                uint32_t ah[2][4];
                uint32_t bb[4][4];
                ldsm_x4(ah[0], a0 + ks * 32);
                if (two) ldsm_x4(ah[1], a1 + ks * 32);
                #pragma unroll
                for (int np = 0; np < 4; ++np)
                    ldsm_x4(bb[np], wt + (uint32_t)np * 2048 + (uint32_t)ks * 256);
                #pragma unroll
                for (int nt = 0; nt < 8; ++nt)
                    mma16816(acc[0][nt], ah[0], bb[nt >> 1][(nt & 1) * 2], bb[nt >> 1][(nt & 1) * 2 + 1]);
                if (two) {
                    #pragma unroll
                    for (int nt = 0; nt < 8; ++nt)
                        mma16816(acc[1][nt], ah[1], bb[nt >> 1][(nt & 1) * 2], bb[nt >> 1][(nt & 1) * 2 + 1]);
                }
            }
        }
    }

    // ---- epilogue ----
    __syncthreads();
    float* epi = (float*)smem;     // [224][66]
    {
        const int g  = lane >> 2;
        const int tg = lane & 3;
        #pragma unroll
        for (int mt = 0; mt < 2; ++mt) {
            if (mt == 0 || two) {
                int tile = t0 + mt;
                #pragma unroll
                for (int nt = 0; nt < 8; ++nt) {
                    int p  = tile * 16 + g;
                    int co = nt * 8 + 2 * tg;
                    *(float2*)&epi[p * 66 + co]       = make_float2(acc[mt][nt][0], acc[mt][nt][1]);
                    *(float2*)&epi[(p + 8) * 66 + co] = make_float2(acc[mt][nt][2], acc[mt][nt][3]);
                }
            }
        }
    }
    __syncthreads();

    #pragma unroll 1
    for (int cog = 0; cog < 8; ++cog) {
        int co = wid + cog * 8;
        float bv = s_bias[co];
        float* op = out + ((size_t)(n * COUT + co)) * HH + (size_t)(by * BS) * H + bx * BS;
        int yy = ly0, xq = lx0;
        #pragma unroll
        for (int rnd = 0; rnd < 7; ++rnd) {
            if (rnd * 32 + lane < BS * BS)
                op[(size_t)yy * H + xq] = epi[(yy * 16 + xq) * 66 + co] + bv;
            yy += 2; xq += 4;
            if (xq >= BS) { xq -= BS; ++yy; }
        }
    }
}

extern "C" void kernel_launch(void* const* d_in, const int* in_sizes, int n_in,
                              void* d_out, int out_size) {
    const float* x    = (const float*)d_in[0];
    const float* mask = (const float*)d_in[1];
    const float* w    = (const float*)d_in[2];
    const float* bias = (const float*)d_in[3];
    float* out = (float*)d_out;

    int N = in_sizes[0] / (CIN * H * H);   // 4
    int nblk = N * NB * NB;

    cudaFuncSetAttribute(sbnet_mma_kernel,
                         cudaFuncAttributeMaxDynamicSharedMemorySize, SMEM_TOTAL);

    sbnet_prep_kernel<<<18 + (nblk + 255) / 256, 256>>>(w, mask, nblk);
    sbnet_mma_kernel<<<dim3(NB * NB, (unsigned)N), NTHR, SMEM_TOTAL>>>(x, bias, out);
}